// round 2
// baseline (speedup 1.0000x reference)
#include <cuda_runtime.h>
#include <math.h>

#define RES      256
#define NPIX     (RES*RES)      // 65536 pixels per camera
#define NCAM     32
#define NB       64
#define CHUNKS   16
#define CHUNK_PIX (NPIX/CHUNKS) // 4096
#define TPB      64
#define NWARP    (TPB/32)       // 2
#define NBINS    132            // rows 0..64: W ; rows 66..131: Base[0..65]

__global__ void spad_zero_out(float* __restrict__ out) {
    int i = blockIdx.x * blockDim.x + threadIdx.x;
    if (i < NCAM * NB) out[i] = 0.0f;
}

__global__ __launch_bounds__(TPB) void spad_main(
    const float* __restrict__ normals,
    const float* __restrict__ inter,
    const float* __restrict__ film,
    const float* __restrict__ cosm,
    float* __restrict__ out,
    float radC, float inv2sig2, float halfInvBin)
{
    __shared__ float sh[NWARP][NBINS][32];
    __shared__ float red[NBINS];

    const int tid  = threadIdx.x;
    const int lane = tid & 31;
    const int wid  = tid >> 5;

    // zero private histograms
    for (int i = tid; i < NWARP * NBINS * 32; i += TPB)
        ((float*)sh)[i] = 0.0f;
    __syncthreads();

    const int cam     = blockIdx.x >> 4;      // / CHUNKS
    const int chunk   = blockIdx.x & (CHUNKS - 1);
    const int base_lp = chunk * CHUNK_PIX;

    const float4* n4 = (const float4*)(normals + (size_t)cam * NPIX * 3);
    const float4* p4 = (const float4*)(inter   + (size_t)cam * NPIX * 3);
    const float4* f4 = (const float4*)film;
    const float4* c4 = (const float4*)cosm;

    float* Wrow = &sh[wid][0][lane];
    float* Brow = &sh[wid][66][lane];

    const float SIG = 3.0f;
    const float E3  = 20.085536923187668f;    // e^3

    // each thread handles 16 groups of 4 consecutive pixels (float4-aligned)
    for (int g = tid; g < CHUNK_PIX / 4; g += TPB) {
        const int lp = base_lp + g * 4;       // local pixel index, %4 == 0
        const int q  = lp >> 2;               // float4 group index

        float4 nA = n4[q*3+0], nB = n4[q*3+1], nC = n4[q*3+2];
        float4 pA = p4[q*3+0], pB = p4[q*3+1], pC = p4[q*3+2];
        float4 fA = f4[q*3+0], fB = f4[q*3+1], fC = f4[q*3+2];
        float4 cV = c4[q];

        float n_[12], p_[12], f_[12], c_[4];
        *(float4*)&n_[0] = nA; *(float4*)&n_[4] = nB; *(float4*)&n_[8] = nC;
        *(float4*)&p_[0] = pA; *(float4*)&p_[4] = pB; *(float4*)&p_[8] = pC;
        *(float4*)&f_[0] = fA; *(float4*)&f_[4] = fB; *(float4*)&f_[8] = fC;
        c_[0] = cV.x; c_[1] = cV.y; c_[2] = cV.z; c_[3] = cV.w;

        #pragma unroll
        for (int u = 0; u < 4; ++u) {
            const float nx = n_[3*u], ny = n_[3*u+1], nz = n_[3*u+2];
            const float px = p_[3*u], py = p_[3*u+1], pz = p_[3*u+2];
            const float fx = f_[3*u], fy = f_[3*u+1], fz = f_[3*u+2];
            const float cm = c_[u];

            // cosine foreshortening, clipped
            float dots = fminf(fmaxf(fx*nx + fy*ny + fz*nz, 0.0f), 1.0f);

            // laser geometry
            const float lx = px - 0.002f;     // 2 * camera_sensor_distance
            const float ly = py;
            const float lz = pz;
            const float lxy2 = lx*lx + ly*ly;
            const float ld2  = lxy2 + lz*lz;
            const float ld   = sqrtf(ld2);
            const float tan2 = __fdividef(lxy2, lz*lz);
            const float lm   = __expf(-tan2 * inv2sig2);

            const float pd  = sqrtf(px*px + py*py + pz*pz);
            const float cm3 = cm * cm * cm;
            const float r   = dots * lm * cm3 * __fdividef(radC, ld2);
            const float d   = (pd + ld) * halfInvBin;   // bin coordinate

            // soft-bin window [kc-5, kc+6]; outside below => S == 1 (Base),
            // outside above => S == 0. Truncation error <= e^-18.
            const int kc = (int)floorf(d);              // NaN -> INT_MIN (clamped safe)
            const int jb = min(max(kc - 5, 0), 65);
            Brow[jb << 5] += r;

            const int ks = max(kc - 5, 0);
            const int ke = min(kc + 6, NB);             // need bins up to 64 (T[64])
            if (ks <= ke) {
                float E = __expf(SIG * ((float)ks - d));  // e^{-3(d-ks)} in [e^-18, 1]
                float* wp = Wrow + (ks << 5);
                #pragma unroll 4
                for (int k = ks; k <= ke; ++k) {
                    *wp += __fdividef(r, 1.0f + E);       // r * sigmoid(3(d-k))
                    wp += 32;
                    E *= E3;                              // shift window by one bin
                }
            }
        }
    }
    __syncthreads();

    // block reduction over (warp, lane); lane-rotated reads stay conflict-free
    for (int bin = tid; bin < NBINS; bin += TPB) {
        float s = 0.0f;
        #pragma unroll
        for (int l = 0; l < 32; ++l) {
            const int ll = (l + tid) & 31;
            s += sh[0][bin][ll] + sh[1][bin][ll];
        }
        red[bin] = s;
    }
    __syncthreads();

    // out[k] = T[k] - T[k+1] = W[k] - W[k+1] + Base[k+1]  (telescoped)
    if (tid < NB) {
        const float o = red[tid] - red[tid + 1] + red[66 + tid + 1];
        atomicAdd(&out[cam * NB + tid], o);
    }
}

extern "C" void kernel_launch(void* const* d_in, const int* in_sizes, int n_in,
                              void* d_out, int out_size) {
    const float* normals = (const float*)d_in[0];   // [32,256,256,3]
    const float* inter   = (const float*)d_in[1];   // [32,256,256,3]
    const float* film    = (const float*)d_in[2];   // [256,256,3]
    const float* cosm    = (const float*)d_in[3];   // [256,256]
    float* out = (float*)d_out;                     // [32,64]

    const double fov    = 33.0 * M_PI / 180.0;
    const double width  = 2.0 * tan(fov / 2.0);
    const float  radC   = (float)(width * width / (M_PI * (double)NPIX));
    const double sig    = tan(21.5 * M_PI / 180.0) / 1.4;
    const float  inv2s2 = (float)(1.0 / (2.0 * sig * sig));
    const float  hib    = (float)(0.5 / 0.0136);    // (1/2) / bin_size

    spad_zero_out<<<(NCAM * NB + 255) / 256, 256>>>(out);
    spad_main<<<NCAM * CHUNKS, TPB>>>(normals, inter, film, cosm, out,
                                      radC, inv2s2, hib);
    (void)in_sizes; (void)n_in; (void)out_size;
}

// round 3
// speedup vs baseline: 1.2169x; 1.2169x over previous
#include <cuda_runtime.h>
#include <math.h>

#define RES       256
#define NPIX      (RES*RES)       // 65536 pixels per camera
#define NCAM      32
#define NB        64
#define CHUNKS    32
#define CHUNK_PIX (NPIX/CHUNKS)   // 2048
#define TPB       128
#define NWARP     (TPB/32)        // 4

__global__ void spad_zero_out(float* __restrict__ out) {
    int i = blockIdx.x * blockDim.x + threadIdx.x;
    if (i < NCAM * NB) out[i] = 0.0f;
}

__global__ __launch_bounds__(TPB, 7) void spad_main(
    const float* __restrict__ normals,
    const float* __restrict__ inter,
    const float* __restrict__ film,
    const float* __restrict__ cosm,
    float* __restrict__ out,
    float radC, float inv2sig2, float halfInvBin)
{
    // per-(warp,lane) private difference-histograms: bank == lane, conflict-free
    __shared__ float sh[NWARP][NB][32];

    const int tid  = threadIdx.x;
    const int lane = tid & 31;
    const int wid  = tid >> 5;

    // zero private histograms
    for (int i = tid; i < NWARP * NB * 32; i += TPB)
        ((float*)sh)[i] = 0.0f;
    __syncthreads();

    const int cam   = blockIdx.x >> 5;          // / CHUNKS
    const int chunk = blockIdx.x & (CHUNKS - 1);

    const float4* n4 = (const float4*)(normals + (size_t)cam * NPIX * 3);
    const float4* p4 = (const float4*)(inter   + (size_t)cam * NPIX * 3);
    const float4* f4 = (const float4*)film;
    const float4* c4 = (const float4*)cosm;

    float* Wrow = &sh[wid][0][lane];

    const float SIG = 3.0f;
    const float E3  = 20.085536923187668f;      // e^3

    // 2048 px per block -> 512 float4-groups, 4 groups per thread
    const int qbase = chunk * (CHUNK_PIX / 4);
    for (int g = tid; g < CHUNK_PIX / 4; g += TPB) {
        const int q = qbase + g;                // float4 group index within camera

        float4 nA = n4[q*3+0], nB = n4[q*3+1], nC = n4[q*3+2];
        float4 pA = p4[q*3+0], pB = p4[q*3+1], pC = p4[q*3+2];
        float4 fA = f4[q*3+0], fB = f4[q*3+1], fC = f4[q*3+2];
        float4 cV = c4[q];

        float n_[12], p_[12], f_[12], c_[4];
        *(float4*)&n_[0] = nA; *(float4*)&n_[4] = nB; *(float4*)&n_[8] = nC;
        *(float4*)&p_[0] = pA; *(float4*)&p_[4] = pB; *(float4*)&p_[8] = pC;
        *(float4*)&f_[0] = fA; *(float4*)&f_[4] = fB; *(float4*)&f_[8] = fC;
        c_[0] = cV.x; c_[1] = cV.y; c_[2] = cV.z; c_[3] = cV.w;

        #pragma unroll
        for (int u = 0; u < 4; ++u) {
            const float nx = n_[3*u], ny = n_[3*u+1], nz = n_[3*u+2];
            const float px = p_[3*u], py = p_[3*u+1], pz = p_[3*u+2];
            const float fx = f_[3*u], fy = f_[3*u+1], fz = f_[3*u+2];
            const float cm = c_[u];

            // cosine foreshortening, clipped
            float dots = fminf(fmaxf(fx*nx + fy*ny + fz*nz, 0.0f), 1.0f);

            // laser geometry
            const float lx = px - 0.002f;       // 2 * camera_sensor_distance
            const float ly = py;
            const float lz = pz;
            const float lxy2 = lx*lx + ly*ly;
            const float ld2  = lxy2 + lz*lz;
            const float ld   = sqrtf(ld2);
            const float tan2 = __fdividef(lxy2, lz*lz);
            const float lm   = __expf(-tan2 * inv2sig2);

            const float pd  = sqrtf(px*px + py*py + pz*pz);
            const float cm3 = cm * cm * cm;
            const float r   = dots * lm * cm3 * __fdividef(radC, ld2);
            const float d   = (pd + ld) * halfInvBin;   // bin coordinate

            // window [kc-5, kc+6]; outside: S==1 below, S==0 above (err <= e^-15)
            // per-pixel telescoped contribution: out[k] += r*(S_k - S_{k+1})
            const int kc = (int)floorf(d);
            const int ks = max(kc - 5, 0);
            const int ke = min(kc + 6, NB);     // S_64 needed for out[63]

            if (ks <= ke) {
                float E    = __expf(SIG * ((float)ks - d));  // e^{3(ks-d)}
                float prev = r;                              // r * S_{ks-1} ~= r
                float* wp  = Wrow + ((ks - 1) << 5);         // bin ks-1 (guarded)
                #pragma unroll 4
                for (int k = ks; k <= ke; ++k) {
                    const float S = __fdividef(r, 1.0f + E); // r * sigmoid(3(d-k))
                    if (k - 1 >= 0) *wp += (prev - S);       // bin k-1 in [0,63]
                    wp += 32; prev = S; E *= E3;
                }
                if (ke <= NB - 1) *wp += prev;               // tail: r*S_ke at bin ke
            }
        }
    }
    __syncthreads();

    // fold warps 1..3 into warp 0's histogram
    float* s0 = (float*)sh;
    for (int i = tid; i < NB * 32; i += TPB)
        s0[i] += s0[i + NB*32] + s0[i + 2*NB*32] + s0[i + 3*NB*32];
    __syncthreads();

    // lane-rotated conflict-free reduction over 32 lanes, then global atomic
    if (tid < NB) {
        float s = 0.0f;
        #pragma unroll
        for (int l = 0; l < 32; ++l)
            s += sh[0][tid][(l + tid) & 31];
        atomicAdd(&out[cam * NB + tid], s);
    }
}

extern "C" void kernel_launch(void* const* d_in, const int* in_sizes, int n_in,
                              void* d_out, int out_size) {
    const float* normals = (const float*)d_in[0];   // [32,256,256,3]
    const float* inter   = (const float*)d_in[1];   // [32,256,256,3]
    const float* film    = (const float*)d_in[2];   // [256,256,3]
    const float* cosm    = (const float*)d_in[3];   // [256,256]
    float* out = (float*)d_out;                     // [32,64]

    const double fov    = 33.0 * M_PI / 180.0;
    const double width  = 2.0 * tan(fov / 2.0);
    const float  radC   = (float)(width * width / (M_PI * (double)NPIX));
    const double sig    = tan(21.5 * M_PI / 180.0) / 1.4;
    const float  inv2s2 = (float)(1.0 / (2.0 * sig * sig));
    const float  hib    = (float)(0.5 / 0.0136);    // (1/2) / bin_size

    spad_zero_out<<<(NCAM * NB + 255) / 256, 256>>>(out);
    spad_main<<<NCAM * CHUNKS, TPB>>>(normals, inter, film, cosm, out,
                                      radC, inv2s2, hib);
    (void)in_sizes; (void)n_in; (void)out_size;
}

// round 6
// speedup vs baseline: 1.3778x; 1.1322x over previous
#include <cuda_runtime.h>
#include <math.h>

#define RES       256
#define NPIX      (RES*RES)       // 65536 pixels per camera
#define NQUAD     (NPIX/4)        // 16384 float4-groups per camera
#define NCAM      32
#define NB        64
#define CAMCHUNK  56              // chunks per camera -> grid 1792 (single wave @13/SM)
#define TPB       64
#define NWARP     (TPB/32)        // 2
#define ROWS      66              // row 0: dummy (k<0); rows 1..64: bins 0..63; row 65: dummy (k>=64)

__global__ void spad_zero_out(float* __restrict__ out) {
    int i = blockIdx.x * blockDim.x + threadIdx.x;
    if (i < NCAM * NB) out[i] = 0.0f;
}

__global__ __launch_bounds__(TPB, 13) void spad_main(
    const float* __restrict__ normals,
    const float* __restrict__ inter,
    const float* __restrict__ film,
    const float* __restrict__ cosm,
    float* __restrict__ out,
    float radC, float inv2sig2, float halfInvBin)
{
    // per-(warp,lane) private difference-histograms: bank == lane, conflict-free
    __shared__ float sh[NWARP][ROWS][32];

    const int tid  = threadIdx.x;
    const int lane = tid & 31;
    const int wid  = tid >> 5;

    for (int i = tid; i < NWARP * ROWS * 32; i += TPB)
        ((float*)sh)[i] = 0.0f;
    __syncthreads();

    const int cam   = blockIdx.x / CAMCHUNK;
    const int chunk = blockIdx.x % CAMCHUNK;
    const int qs    = (NQUAD * chunk)       / CAMCHUNK;
    const int qe    = (NQUAD * (chunk + 1)) / CAMCHUNK;

    const float4* n4 = (const float4*)(normals + (size_t)cam * NPIX * 3);
    const float4* p4 = (const float4*)(inter   + (size_t)cam * NPIX * 3);
    const float4* f4 = (const float4*)film;
    const float4* c4 = (const float4*)cosm;

    float* Wbase = &sh[wid][0][lane];

    const float E3 = 20.085536923187668f;   // e^3

    for (int q = qs + tid; q < qe; q += TPB) {
        float4 nA = n4[q*3+0], nB = n4[q*3+1], nC = n4[q*3+2];
        float4 pA = p4[q*3+0], pB = p4[q*3+1], pC = p4[q*3+2];
        float4 fA = f4[q*3+0], fB = f4[q*3+1], fC = f4[q*3+2];
        float4 cV = c4[q];

        float n_[12], p_[12], f_[12], c_[4];
        *(float4*)&n_[0] = nA; *(float4*)&n_[4] = nB; *(float4*)&n_[8] = nC;
        *(float4*)&p_[0] = pA; *(float4*)&p_[4] = pB; *(float4*)&p_[8] = pC;
        *(float4*)&f_[0] = fA; *(float4*)&f_[4] = fB; *(float4*)&f_[8] = fC;
        c_[0] = cV.x; c_[1] = cV.y; c_[2] = cV.z; c_[3] = cV.w;

        #pragma unroll
        for (int u = 0; u < 4; ++u) {
            const float nx = n_[3*u], ny = n_[3*u+1], nz = n_[3*u+2];
            const float px = p_[3*u], py = p_[3*u+1], pz = p_[3*u+2];
            const float fx = f_[3*u], fy = f_[3*u+1], fz = f_[3*u+2];
            const float cm = c_[u];

            float dots = fminf(fmaxf(fx*nx + fy*ny + fz*nz, 0.0f), 1.0f);

            const float lx = px - 0.002f;     // 2 * camera_sensor_distance
            const float ly = py;
            const float lz = pz;
            const float lxy2 = lx*lx + ly*ly;
            const float ld2  = lxy2 + lz*lz;
            const float ld   = sqrtf(ld2);
            const float tan2 = __fdividef(lxy2, lz*lz);
            const float lm   = __expf(-tan2 * inv2sig2);

            const float pd  = sqrtf(px*px + py*py + pz*pz);
            const float cm3 = cm * cm * cm;
            const float r   = dots * lm * cm3 * __fdividef(radC, ld2);
            const float d   = (pd + ld) * halfInvBin;   // bin coordinate (>= 0)

            const int kc = __float2int_rd(d);

            // Uniform 11-bin window, branchless. Bin b = kc-5 .. kc+5 receives
            // r*(S_b - S_{b+1}); S_{kc-5} ~= 1 (err <= e^-15), S_{kc+6}
            // computed naturally (~0). Out-of-range bins clamp to dummy rows.
            float G    = __expf(3.0f * ((float)kc - d - 5.0f)); // e^{-3(f+5)}
            float prev = r;
            int   b    = kc - 5;
            #pragma unroll
            for (int j = 0; j < 11; ++j) {
                G *= E3;                                  // G at k = b+1
                const float S  = __fdividef(r, 1.0f + G); // r * sigmoid(3(d-b-1))
                const int   rb = min(max(b, -1), 64) + 1; // clamp into [0,65]
                Wbase[rb * 32] += prev - S;
                prev = S; ++b;
            }
        }
    }
    __syncthreads();

    // fold warp 1 into warp 0
    float* s0 = (float*)sh;
    for (int i = tid; i < ROWS * 32; i += TPB)
        s0[i] += s0[i + ROWS * 32];
    __syncthreads();

    // lane-rotated conflict-free reduction; bins 0..63 live in rows 1..64
    if (tid < NB) {
        float s = 0.0f;
        #pragma unroll
        for (int l = 0; l < 32; ++l)
            s += sh[0][tid + 1][(l + tid) & 31];
        atomicAdd(&out[cam * NB + tid], s);
    }
}

extern "C" void kernel_launch(void* const* d_in, const int* in_sizes, int n_in,
                              void* d_out, int out_size) {
    const float* normals = (const float*)d_in[0];   // [32,256,256,3]
    const float* inter   = (const float*)d_in[1];   // [32,256,256,3]
    const float* film    = (const float*)d_in[2];   // [256,256,3]
    const float* cosm    = (const float*)d_in[3];   // [256,256]
    float* out = (float*)d_out;                     // [32,64]

    const double fov    = 33.0 * M_PI / 180.0;
    const double width  = 2.0 * tan(fov / 2.0);
    const float  radC   = (float)(width * width / (M_PI * (double)NPIX));
    const double sig    = tan(21.5 * M_PI / 180.0) / 1.4;
    const float  inv2s2 = (float)(1.0 / (2.0 * sig * sig));
    const float  hib    = (float)(0.5 / 0.0136);    // (1/2) / bin_size

    spad_zero_out<<<(NCAM * NB + 255) / 256, 256>>>(out);
    spad_main<<<NCAM * CAMCHUNK, TPB>>>(normals, inter, film, cosm, out,
                                        radC, inv2s2, hib);
    (void)in_sizes; (void)n_in; (void)out_size;
}

// round 7
// speedup vs baseline: 1.6208x; 1.1764x over previous
#include <cuda_runtime.h>
#include <math.h>

#define RES       256
#define NPIX      (RES*RES)       // 65536 pixels per camera
#define NQUAD     (NPIX/4)        // 16384 float4-groups per camera
#define NCAM      32
#define NB        64
#define CAMCHUNK  56              // grid 1792 = single wave @13 blocks/SM
#define TPB       64
#define NWARP     (TPB/32)        // 2
#define ROWS      66              // row 0: dummy(k<0); 1..64: bins 0..63; 65: dummy(k>=64)

__global__ void spad_zero_out(float* __restrict__ out) {
    int i = blockIdx.x * blockDim.x + threadIdx.x;
    if (i < NCAM * NB) out[i] = 0.0f;
}

__global__ __launch_bounds__(TPB, 13) void spad_main(
    const float* __restrict__ normals,
    const float* __restrict__ inter,
    const float* __restrict__ film,
    const float* __restrict__ cosm,
    float* __restrict__ out,
    float radC, float inv2sig2, float halfInvBin)
{
    // per-(warp,lane) private difference-histograms: bank == lane, conflict-free
    __shared__ float sh[NWARP][ROWS][32];

    const int tid  = threadIdx.x;
    const int lane = tid & 31;
    const int wid  = tid >> 5;

    for (int i = tid; i < NWARP * ROWS * 32; i += TPB)
        ((float*)sh)[i] = 0.0f;
    __syncthreads();

    const int cam   = blockIdx.x / CAMCHUNK;
    const int chunk = blockIdx.x % CAMCHUNK;
    const int qs    = (NQUAD * chunk)       / CAMCHUNK;
    const int qe    = (NQUAD * (chunk + 1)) / CAMCHUNK;

    const float4* n4 = (const float4*)(normals + (size_t)cam * NPIX * 3);
    const float4* p4 = (const float4*)(inter   + (size_t)cam * NPIX * 3);
    const float4* f4 = (const float4*)film;
    const float4* c4 = (const float4*)cosm;

    float* Wbase = &sh[wid][0][lane];

    const float E3 = 20.085536923187668f;   // e^3

    for (int q = qs + tid; q < qe; q += TPB) {
        float4 nA = n4[q*3+0], nB = n4[q*3+1], nC = n4[q*3+2];
        float4 pA = p4[q*3+0], pB = p4[q*3+1], pC = p4[q*3+2];
        float4 fA = f4[q*3+0], fB = f4[q*3+1], fC = f4[q*3+2];
        float4 cV = c4[q];

        float n_[12], p_[12], f_[12], c_[4];
        *(float4*)&n_[0] = nA; *(float4*)&n_[4] = nB; *(float4*)&n_[8] = nC;
        *(float4*)&p_[0] = pA; *(float4*)&p_[4] = pB; *(float4*)&p_[8] = pC;
        *(float4*)&f_[0] = fA; *(float4*)&f_[4] = fB; *(float4*)&f_[8] = fC;
        c_[0] = cV.x; c_[1] = cV.y; c_[2] = cV.z; c_[3] = cV.w;

        #pragma unroll
        for (int u = 0; u < 4; ++u) {
            const float nx = n_[3*u], ny = n_[3*u+1], nz = n_[3*u+2];
            const float px = p_[3*u], py = p_[3*u+1], pz = p_[3*u+2];
            const float fx = f_[3*u], fy = f_[3*u+1], fz = f_[3*u+2];
            const float cm = c_[u];

            float dots = fminf(fmaxf(fx*nx + fy*ny + fz*nz, 0.0f), 1.0f);

            const float lx = px - 0.002f;     // 2 * camera_sensor_distance
            const float ly = py;
            const float lz = pz;
            const float lxy2 = lx*lx + ly*ly;
            const float ld2  = lxy2 + lz*lz;
            const float ld   = sqrtf(ld2);
            const float tan2 = __fdividef(lxy2, lz*lz);
            const float lm   = __expf(-tan2 * inv2sig2);

            const float pd  = sqrtf(px*px + py*py + pz*pz);
            const float cm3 = cm * cm * cm;
            const float r   = dots * lm * cm3 * __fdividef(radC, ld2);
            const float d   = (pd + ld) * halfInvBin;   // bin coordinate (>= 0)

            const int kc = __float2int_rd(d);

            // 9-bin window kc-4..kc+4: bin b gets r*(S_b - S_{b+1}).
            // S_{kc-4} ~= 1 (err <= e^-12), leftover tail r*S_{kc+5} <= 6e-6*r dropped.
            float G    = __expf(3.0f * ((float)kc - d - 4.0f));
            float prev = r;

            if (kc >= 4 && kc <= 59) {
                // fast path: whole window inside bins 0..63 -> pure pointer walk
                float* wp = Wbase + ((kc - 3) << 5);     // row of bin kc-4
                #pragma unroll
                for (int j = 0; j < 9; ++j) {
                    G *= E3;
                    const float S = __fdividef(r, 1.0f + G);
                    *wp += prev - S;
                    wp += 32;
                    prev = S;
                }
            } else {
                // rare path: clamp out-of-range bins into dummy rows 0 / 65
                int b = kc - 4;
                #pragma unroll
                for (int j = 0; j < 9; ++j) {
                    G *= E3;
                    const float S  = __fdividef(r, 1.0f + G);
                    const int   rb = min(max(b, -1), 64) + 1;
                    Wbase[rb * 32] += prev - S;
                    prev = S; ++b;
                }
            }
        }
    }
    __syncthreads();

    // fold warp 1 into warp 0
    float* s0 = (float*)sh;
    for (int i = tid; i < ROWS * 32; i += TPB)
        s0[i] += s0[i + ROWS * 32];
    __syncthreads();

    // lane-rotated conflict-free reduction; bins 0..63 live in rows 1..64
    if (tid < NB) {
        float s = 0.0f;
        #pragma unroll
        for (int l = 0; l < 32; ++l)
            s += sh[0][tid + 1][(l + tid) & 31];
        atomicAdd(&out[cam * NB + tid], s);
    }
}

extern "C" void kernel_launch(void* const* d_in, const int* in_sizes, int n_in,
                              void* d_out, int out_size) {
    const float* normals = (const float*)d_in[0];   // [32,256,256,3]
    const float* inter   = (const float*)d_in[1];   // [32,256,256,3]
    const float* film    = (const float*)d_in[2];   // [256,256,3]
    const float* cosm    = (const float*)d_in[3];   // [256,256]
    float* out = (float*)d_out;                     // [32,64]

    const double fov    = 33.0 * M_PI / 180.0;
    const double width  = 2.0 * tan(fov / 2.0);
    const float  radC   = (float)(width * width / (M_PI * (double)NPIX));
    const double sig    = tan(21.5 * M_PI / 180.0) / 1.4;
    const float  inv2s2 = (float)(1.0 / (2.0 * sig * sig));
    const float  hib    = (float)(0.5 / 0.0136);    // (1/2) / bin_size

    spad_zero_out<<<(NCAM * NB + 255) / 256, 256>>>(out);
    spad_main<<<NCAM * CAMCHUNK, TPB>>>(normals, inter, film, cosm, out,
                                        radC, inv2s2, hib);
    (void)in_sizes; (void)n_in; (void)out_size;
}